// round 1
// baseline (speedup 1.0000x reference)
#include <cuda_runtime.h>
#include <math.h>

// Problem constants
#define Bq 16
#define Tq 750
#define Fq 4096
#define Cq 20
#define Kq 93           // T / 8
#define F4 (Fq/4)       // 1024 float4 per row
#define NROWS (Bq*Tq)   // 12000

// Output layout (concatenated in reference return order, float32)
#define OFF_SA   0L
#define OFF_SB   320L
#define OFF_FA   640L
#define OFF_FB   (OFF_FA + (long)Bq*Kq*Fq)      // 6,095,488
#define OFF_FEAT (OFF_FB + (long)Bq*Kq*Fq)      // 12,190,336
#define OFF_CS   (OFF_FEAT + (long)NROWS*Fq)    // 61,342,336

// Scratch (static device globals; no runtime allocation)
__device__ float g_cas[NROWS*Cq];
__device__ float g_mag[NROWS];
__device__ int   g_idx_act[Bq*Kq];
__device__ int   g_idx_bkg[Bq*Kq];
__device__ float g_sa[Bq*Cq];
__device__ float g_sb[Bq*Cq];

// ---------------------------------------------------------------------------
// K1: fused stream kernel. Each warp owns 2 rows (b,t):
//   - masked = x * mask_cls  (registers only)
//   - cas[c] = sum_f masked * W[c][f]  (20 classes, 2 rows -> 40 accumulators)
//   - sumsq  = sum_f x*x  -> mag
//   - features output = copy of x
//   - per-row softmax over C=20 -> cas_softmax output; raw cas -> scratch
// ---------------------------------------------------------------------------
__global__ __launch_bounds__(256) void k_main(const float4* __restrict__ x4,
                                              const float4* __restrict__ m4,
                                              const float4* __restrict__ w4,
                                              float* __restrict__ out)
{
    const int warp = (blockIdx.x * blockDim.x + threadIdx.x) >> 5;
    const int lane = threadIdx.x & 31;
    const int r0 = warp * 2;
    const int r1 = r0 + 1;
    if (r1 >= NROWS) return;

    const float4* __restrict__ xa = x4 + (long)r0 * F4;
    const float4* __restrict__ xb = x4 + (long)r1 * F4;
    const float4* __restrict__ ma = m4 + (long)r0 * F4;
    const float4* __restrict__ mb = m4 + (long)r1 * F4;
    float4* __restrict__ fo0 = reinterpret_cast<float4*>(out + OFF_FEAT) + (long)r0 * F4;
    float4* __restrict__ fo1 = reinterpret_cast<float4*>(out + OFF_FEAT) + (long)r1 * F4;

    float acc0[Cq], acc1[Cq];
#pragma unroll
    for (int c = 0; c < Cq; c++) { acc0[c] = 0.f; acc1[c] = 0.f; }
    float sq0 = 0.f, sq1 = 0.f;

    for (int i = 0; i < F4 / 32; i++) {
        const int j = lane + 32 * i;
        float4 a  = xa[j];
        float4 am = ma[j];
        float4 b  = xb[j];
        float4 bm = mb[j];
        fo0[j] = a;
        fo1[j] = b;
        float4 pa, pb;
        pa.x = a.x*am.x; pa.y = a.y*am.y; pa.z = a.z*am.z; pa.w = a.w*am.w;
        pb.x = b.x*bm.x; pb.y = b.y*bm.y; pb.z = b.z*bm.z; pb.w = b.w*bm.w;
        sq0 = fmaf(a.x,a.x, fmaf(a.y,a.y, fmaf(a.z,a.z, fmaf(a.w,a.w, sq0))));
        sq1 = fmaf(b.x,b.x, fmaf(b.y,b.y, fmaf(b.z,b.z, fmaf(b.w,b.w, sq1))));
#pragma unroll
        for (int c = 0; c < Cq; c++) {
            float4 w = w4[c * F4 + j];
            acc0[c] = fmaf(pa.x,w.x, fmaf(pa.y,w.y, fmaf(pa.z,w.z, fmaf(pa.w,w.w, acc0[c]))));
            acc1[c] = fmaf(pb.x,w.x, fmaf(pb.y,w.y, fmaf(pb.z,w.z, fmaf(pb.w,w.w, acc1[c]))));
        }
    }

    // warp tree reduction (butterfly)
#pragma unroll
    for (int off = 16; off > 0; off >>= 1) {
        sq0 += __shfl_xor_sync(0xffffffffu, sq0, off);
        sq1 += __shfl_xor_sync(0xffffffffu, sq1, off);
#pragma unroll
        for (int c = 0; c < Cq; c++) {
            acc0[c] += __shfl_xor_sync(0xffffffffu, acc0[c], off);
            acc1[c] += __shfl_xor_sync(0xffffffffu, acc1[c], off);
        }
    }

    // lane c (<20) takes class c (static selection, no dynamic reg indexing)
    float v0 = 0.f, v1 = 0.f;
#pragma unroll
    for (int c = 0; c < Cq; c++) {
        if (lane == c) { v0 = acc0[c]; v1 = acc1[c]; }
    }

    // softmax over C=20 across lanes
    float m0 = (lane < Cq) ? v0 : -INFINITY;
    float m1 = (lane < Cq) ? v1 : -INFINITY;
#pragma unroll
    for (int off = 16; off > 0; off >>= 1) {
        m0 = fmaxf(m0, __shfl_xor_sync(0xffffffffu, m0, off));
        m1 = fmaxf(m1, __shfl_xor_sync(0xffffffffu, m1, off));
    }
    float e0 = (lane < Cq) ? expf(v0 - m0) : 0.f;
    float e1 = (lane < Cq) ? expf(v1 - m1) : 0.f;
    float s0 = e0, s1 = e1;
#pragma unroll
    for (int off = 16; off > 0; off >>= 1) {
        s0 += __shfl_xor_sync(0xffffffffu, s0, off);
        s1 += __shfl_xor_sync(0xffffffffu, s1, off);
    }
    if (lane < Cq) {
        out[OFF_CS + (long)r0 * Cq + lane] = e0 / s0;
        out[OFF_CS + (long)r1 * Cq + lane] = e1 / s1;
        g_cas[r0 * Cq + lane] = v0;
        g_cas[r1 * Cq + lane] = v1;
    }
    if (lane == 0) {
        g_mag[r0] = sqrtf(sq0);
        g_mag[r1] = sqrtf(sq1);
    }
}

// ---------------------------------------------------------------------------
// K2: per-batch selection. Stable descending top-93 of mag*sel and
// (max(mag)-mag)*sel via rank counting (matches jax.lax.top_k tie-break).
// ---------------------------------------------------------------------------
__global__ __launch_bounds__(256) void k_select(const float* __restrict__ sel)
{
    const int b = blockIdx.x;
    const int tid = threadIdx.x;
    __shared__ float va[Tq];
    __shared__ float vr[Tq];
    __shared__ float red[256];

    // load mags, block max
    float lmax = -INFINITY;
    for (int t = tid; t < Tq; t += 256) {
        float m = g_mag[b * Tq + t];
        va[t] = m;                 // temporarily raw mag
        lmax = fmaxf(lmax, m);
    }
    red[tid] = lmax;
    __syncthreads();
    for (int s = 128; s > 0; s >>= 1) {
        if (tid < s) red[tid] = fmaxf(red[tid], red[tid + s]);
        __syncthreads();
    }
    const float mx = red[0];
    __syncthreads();

    for (int t = tid; t < Tq; t += 256) {
        float m = va[t];
        float s = sel[b * Tq + t];
        vr[t] = (mx - m) * s;
        va[t] = m * s;
    }
    __syncthreads();

    for (int t = tid; t < Tq; t += 256) {
        float x = va[t];
        float y = vr[t];
        int ra = 0, rb = 0;
        for (int j = 0; j < Tq; j++) {
            float u = va[j];
            float w = vr[j];
            ra += (u > x) || (u == x && j < t);
            rb += (w > y) || (w == y && j < t);
        }
        if (ra < Kq) g_idx_act[b * Kq + ra] = t;
        if (rb < Kq) g_idx_bkg[b * Kq + rb] = t;
    }
}

// ---------------------------------------------------------------------------
// K3: gather feat_act / feat_bkg rows from x.
// grid.x = B*K (row), grid.y = 0 -> act, 1 -> bkg
// ---------------------------------------------------------------------------
__global__ __launch_bounds__(128) void k_gather(const float4* __restrict__ x4,
                                                float* __restrict__ out)
{
    const int i = blockIdx.x;           // b*93 + k
    const int b = i / Kq;
    const int t = (blockIdx.y == 0) ? g_idx_act[i] : g_idx_bkg[i];
    const float4* __restrict__ src = x4 + ((long)(b * Tq + t)) * F4;
    float4* __restrict__ dst =
        reinterpret_cast<float4*>(out + (blockIdx.y == 0 ? OFF_FA : OFF_FB)) + (long)i * F4;
#pragma unroll
    for (int j = threadIdx.x; j < F4; j += 128) dst[j] = src[j];
}

// ---------------------------------------------------------------------------
// K4: per-(b,c): mean of top-93 cas over T (score_act pre-softmax) and
// mean of cas at idx_bkg (score_bkg pre-softmax).
// ---------------------------------------------------------------------------
__global__ __launch_bounds__(256) void k_scores()
{
    const int bc = blockIdx.x;          // b*20 + c
    const int b = bc / Cq;
    const int c = bc % Cq;
    const int tid = threadIdx.x;
    __shared__ float col[Tq];
    __shared__ float redA[256];
    __shared__ float redB[256];

    for (int t = tid; t < Tq; t += 256)
        col[t] = g_cas[(b * Tq + t) * Cq + c];
    __syncthreads();

    float sa = 0.f;
    for (int t = tid; t < Tq; t += 256) {
        float x = col[t];
        int r = 0;
        for (int j = 0; j < Tq; j++) {
            float u = col[j];
            r += (u > x) || (u == x && j < t);
        }
        if (r < Kq) sa += x;
    }
    float sb = 0.f;
    for (int i = tid; i < Kq; i += 256)
        sb += col[g_idx_bkg[b * Kq + i]];

    redA[tid] = sa;
    redB[tid] = sb;
    __syncthreads();
    for (int s = 128; s > 0; s >>= 1) {
        if (tid < s) { redA[tid] += redA[tid + s]; redB[tid] += redB[tid + s]; }
        __syncthreads();
    }
    if (tid == 0) {
        g_sa[bc] = redA[0] / (float)Kq;
        g_sb[bc] = redB[0] / (float)Kq;
    }
}

// ---------------------------------------------------------------------------
// K5: softmax over C for score_act / score_bkg (one warp per batch).
// ---------------------------------------------------------------------------
__global__ __launch_bounds__(32) void k_softmax_scores(float* __restrict__ out)
{
    const int b = blockIdx.x;
    const int lane = threadIdx.x;
    float va = (lane < Cq) ? g_sa[b * Cq + lane] : -INFINITY;
    float vb = (lane < Cq) ? g_sb[b * Cq + lane] : -INFINITY;
    float ma = va, mb = vb;
#pragma unroll
    for (int off = 16; off > 0; off >>= 1) {
        ma = fmaxf(ma, __shfl_xor_sync(0xffffffffu, ma, off));
        mb = fmaxf(mb, __shfl_xor_sync(0xffffffffu, mb, off));
    }
    float ea = (lane < Cq) ? expf(va - ma) : 0.f;
    float eb = (lane < Cq) ? expf(vb - mb) : 0.f;
    float sa = ea, sb = eb;
#pragma unroll
    for (int off = 16; off > 0; off >>= 1) {
        sa += __shfl_xor_sync(0xffffffffu, sa, off);
        sb += __shfl_xor_sync(0xffffffffu, sb, off);
    }
    if (lane < Cq) {
        out[OFF_SA + b * Cq + lane] = ea / sa;
        out[OFF_SB + b * Cq + lane] = eb / sb;
    }
}

// ---------------------------------------------------------------------------
extern "C" void kernel_launch(void* const* d_in, const int* in_sizes, int n_in,
                              void* d_out, int out_size)
{
    const float* x   = (const float*)d_in[0];   // (B,T,F)
    const float* W   = (const float*)d_in[1];   // (C,F)
    const float* mk  = (const float*)d_in[2];   // (B,T,F)
    const float* sel = (const float*)d_in[3];   // (B,T)
    float* out = (float*)d_out;

    k_main<<<NROWS / 16, 256>>>((const float4*)x, (const float4*)mk,
                                (const float4*)W, out);
    k_select<<<Bq, 256>>>(sel);
    {
        dim3 grid(Bq * Kq, 2);
        k_gather<<<grid, 128>>>((const float4*)x, out);
    }
    k_scores<<<Bq * Cq, 256>>>();
    k_softmax_scores<<<Bq, 32>>>(out);
}